// round 1
// baseline (speedup 1.0000x reference)
#include <cuda_runtime.h>

// Problem constants (fixed by the reference)
#define NT   1024          // N = I + O + R
#define NI   64            // I
#define NO   64            // O
#define NJ   960           // columns 64..1023 (the only ones ever needed)
#define WARM 25
#define INVN (1.0f/1024.0f)

// -------------------- device scratch (no allocations allowed) ----------------
__device__ float g_Sd[NT * NJ];        // sig_diff[k][j-64], rows 64..127 masked to 0
__device__ float g_Wp[NI * NJ];        // (delta/N) * sig_diff[k<64][j-64]  (pre-scaled)
__device__ float g_reg[2][NT];         // ping-pong unnormalized warmup state (entries >=64 used)
__device__ float g_spart[WARM + 2][8]; // deterministic per-block partial sums of s
__device__ float g_c0[NJ];             // warm-state constant offset for the batch step

// -------------------- f32x2 packed-FMA helpers (sm_103a) ---------------------
__device__ __forceinline__ unsigned long long pk2(float x) {
    unsigned long long r;
    asm("mov.b64 %0, {%1, %2};" : "=l"(r) : "f"(x), "f"(x));
    return r;
}
__device__ __forceinline__ void fma2(unsigned long long& d, unsigned long long a,
                                     unsigned long long b) {
    asm("fma.rn.f32x2 %0, %1, %2, %0;" : "+l"(d) : "l"(a), "l"(b));
}
__device__ __forceinline__ void upk2(unsigned long long v, float& lo, float& hi) {
    asm("mov.b64 {%0, %1}, %2;" : "=f"(lo), "=f"(hi) : "l"(v));
}

// -------------------- 1) signatures -----------------------------------------
// Sd[k][jj] = mask(k) * (exp(-b|e_k - id_j|) - exp(-b|i_k - id_j|)),  j = 64+jj
// Also writes W (rows k<64) pre-scaled by delta/N.
__global__ void k_sig(const float* __restrict__ ident, const float* __restrict__ enh,
                      const float* __restrict__ inh, const float* __restrict__ beta,
                      const float* __restrict__ delta) {
    int jj = blockIdx.x * blockDim.x + threadIdx.x;
    if (jj >= NJ) return;
    int k = blockIdx.y;
    float v = 0.f;
    if (!(k >= NI && k < NI + NO)) {
        float b   = beta[0];
        float idv = ident[NI + jj];
        v = expf(-b * fabsf(enh[k] - idv)) - expf(-b * fabsf(inh[k] - idv));
    }
    g_Sd[k * NJ + jj] = v;
    if (k < NI) g_Wp[k * NJ + jj] = v * (delta[0] * INVN);
}

// -------------------- 2) init ------------------------------------------------
__global__ void k_init() {
    int t = threadIdx.x;
    g_reg[0][t] = INVN;                       // conc0 = 1/N (entries <64 never read)
    if (t < 8) g_spart[0][t] = (t == 0) ? 1.f : 0.f;   // s_0 = 1 -> inv_s = 1
}

// -------------------- 3) one warmup step (x25) -------------------------------
// conc[k] = (k<64) ? 1/N : reg_in[k] * inv_s   (normalization deferred via s)
// t_j = relu(conc[j] + (d/N) * sum_k conc[k]*Sd[k][j]);  s_next = sum_j t_j
__global__ void k_step(int it, const float* __restrict__ delta) {
    __shared__ float sc[NT];
    __shared__ float wsum[4];
    const float* rin  = g_reg[it & 1];
    float*       rout = g_reg[(it + 1) & 1];
    int tid = threadIdx.x;
    int gid = blockIdx.x * blockDim.x + tid;

    float s = 0.f;
    #pragma unroll
    for (int q = 0; q < 8; ++q) s += g_spart[it][q];
    float inv_s = (s > 0.f) ? 1.f / s : 1.f;

    for (int k = tid; k < NT; k += blockDim.x)
        sc[k] = (k < NI) ? INVN : rin[k] * inv_s;
    __syncthreads();

    float t = 0.f;
    if (gid < NJ) {
        const float* col = g_Sd + gid;
        float sum = 0.f;
        #pragma unroll 8
        for (int k = 0; k < NT; ++k) sum += sc[k] * col[k * NJ];
        t = fmaxf(sc[NI + gid] + delta[0] * INVN * sum, 0.f);
        rout[NI + gid] = t;
    }
    // deterministic block reduction -> fixed partial slot
    #pragma unroll
    for (int off = 16; off > 0; off >>= 1) t += __shfl_xor_sync(0xffffffffu, t, off);
    if ((tid & 31) == 0) wsum[tid >> 5] = t;
    __syncthreads();
    if (tid == 0) g_spart[it + 1][blockIdx.x] = wsum[0] + wsum[1] + wsum[2] + wsum[3];
}

// -------------------- 4) batch-step constant ---------------------------------
// c0[jj] = cw[64+jj] + (d/N) * sum_{k>=64} cw[k] * Sd[k][jj]
__global__ void k_c0(const float* __restrict__ delta) {
    __shared__ float sc[NT];
    const float* rin = g_reg[WARM & 1];
    int tid = threadIdx.x;
    int gid = blockIdx.x * blockDim.x + tid;

    float s = 0.f;
    #pragma unroll
    for (int q = 0; q < 8; ++q) s += g_spart[WARM][q];
    float inv_s = (s > 0.f) ? 1.f / s : 1.f;

    for (int k = tid; k < NT; k += blockDim.x)
        sc[k] = (k < NI) ? 0.f : rin[k] * inv_s;
    __syncthreads();

    if (gid < NJ) {
        const float* col = g_Sd + gid;
        float sum = 0.f;
        #pragma unroll 8
        for (int k = 0; k < NT; ++k) sum += sc[k] * col[k * NJ];
        g_c0[gid] = sc[NI + gid] + delta[0] * INVN * sum;
    }
}

// -------------------- 5) fused batch step ------------------------------------
// Per row b: t_j = relu(c0[j] + inputs[b,:64] @ Wp[:, j]);  s = sum_j t_j;
// out[b, 0..63] = t_{64..127} * (s>0 ? 1/s : 1)
// Block: 64 rows x all 960 cols (15 tiles of 64). 256 threads = 16x16,
// micro-tile 4 rows x 4 cols, accumulated as f32x2 column pairs.
__global__ __launch_bounds__(256) void k_batch(const float* __restrict__ in,
                                               float* __restrict__ out) {
    __shared__ __align__(16) float Vs[64][68];   // [k][m], padded
    __shared__ __align__(16) float Ws[64][64];   // [k][jloc]
    __shared__ float c0s[64];

    int tid = threadIdx.x;
    int m0  = blockIdx.x * 64;

    for (int r = tid; r < 64 * 64; r += 256) {
        int m = r >> 6, k = r & 63;
        Vs[k][m] = in[(m0 + m) * 64 + k];
    }

    int ty = tid >> 4, tx = tid & 15;
    float rsum[4] = {0.f, 0.f, 0.f, 0.f};
    float outv[16];

    for (int jt = 0; jt < 15; ++jt) {
        __syncthreads();
        for (int r = tid; r < 64 * 64; r += 256) {
            int k = r >> 6, l = r & 63;
            Ws[k][l] = g_Wp[k * NJ + jt * 64 + l];
        }
        if (tid < 64) c0s[tid] = g_c0[jt * 64 + tid];
        __syncthreads();

        unsigned long long acc[8];
        #pragma unroll
        for (int u = 0; u < 8; ++u) acc[u] = 0ull;

        #pragma unroll 8
        for (int k = 0; k < 64; ++k) {
            float4 rv = *(const float4*)&Vs[k][ty * 4];
            const unsigned long long* wp =
                (const unsigned long long*)&Ws[k][tx * 4];
            unsigned long long w01 = wp[0], w23 = wp[1];
            unsigned long long v;
            v = pk2(rv.x); fma2(acc[0], v, w01); fma2(acc[1], v, w23);
            v = pk2(rv.y); fma2(acc[2], v, w01); fma2(acc[3], v, w23);
            v = pk2(rv.z); fma2(acc[4], v, w01); fma2(acc[5], v, w23);
            v = pk2(rv.w); fma2(acc[6], v, w01); fma2(acc[7], v, w23);
        }

        #pragma unroll
        for (int i = 0; i < 4; ++i) {
            #pragma unroll
            for (int u2 = 0; u2 < 2; ++u2) {
                float a0, a1;
                upk2(acc[i * 2 + u2], a0, a1);
                int c = tx * 4 + u2 * 2;
                float t0 = fmaxf(c0s[c]     + a0, 0.f);
                float t1 = fmaxf(c0s[c + 1] + a1, 0.f);
                rsum[i] += t0 + t1;
                if (jt == 0) {
                    outv[i * 4 + u2 * 2]     = t0;
                    outv[i * 4 + u2 * 2 + 1] = t1;
                }
            }
        }
    }

    // row sums: reduce over the 16 tx lanes (lane-group of 16 inside each warp)
    #pragma unroll
    for (int i = 0; i < 4; ++i) {
        #pragma unroll
        for (int off = 8; off > 0; off >>= 1)
            rsum[i] += __shfl_xor_sync(0xffffffffu, rsum[i], off);
    }

    #pragma unroll
    for (int i = 0; i < 4; ++i) {
        float s   = rsum[i];
        float inv = (s > 0.f) ? 1.f / s : 1.f;
        int b = m0 + ty * 4 + i;
        float4 o;
        o.x = outv[i * 4 + 0] * inv;
        o.y = outv[i * 4 + 1] * inv;
        o.z = outv[i * 4 + 2] * inv;
        o.w = outv[i * 4 + 3] * inv;
        *(float4*)&out[b * 64 + tx * 4] = o;
    }
}

// -------------------- launch -------------------------------------------------
extern "C" void kernel_launch(void* const* d_in, const int* in_sizes, int n_in,
                              void* d_out, int out_size) {
    const float* inputs = (const float*)d_in[0];
    const float* ident  = (const float*)d_in[1];
    const float* enh    = (const float*)d_in[2];
    const float* inh    = (const float*)d_in[3];
    const float* beta   = (const float*)d_in[4];
    const float* delta  = (const float*)d_in[5];
    float* out = (float*)d_out;
    int B = in_sizes[0] / NI;   // 16384

    k_sig<<<dim3(4, NT), 256>>>(ident, enh, inh, beta, delta);
    k_init<<<1, NT>>>();
    for (int it = 0; it < WARM; ++it)
        k_step<<<8, 128>>>(it, delta);
    k_c0<<<8, 128>>>(delta);
    k_batch<<<B / 64, 256>>>(inputs, out);
}

// round 2
// speedup vs baseline: 5.1548x; 5.1548x over previous
#include <cuda_runtime.h>

// Problem constants (fixed by the reference)
#define NT   1024          // N = I + O + R
#define NI   64            // I
#define NO   64            // O
#define NJ   960           // columns 64..1023 (the only ones ever needed)
#define NA   960           // active rows: k<64 or 128<=k<1024
#define WARM 25
#define INVN (1.0f/1024.0f)

// -------------------- device scratch (no allocations allowed) ----------------
__device__ float g_Wp[NI * NJ];     // (delta/N) * sig_diff[k<64][j]  (pre-scaled)
__device__ float g_c0[NJ];          // warm-state constant offset for the batch step
// prep outputs (m=0: enhancers, m=1: inhibitors)
__device__ float g_cp[2][NA];       // exp(+beta * x_sorted)
__device__ float g_cm[2][NA];       // exp(-beta * x_sorted)
__device__ int   g_gx[2][NA];       // original conc index k for sorted slot
__device__ int   g_pos[2][NJ];      // # sorted values <= id_j
__device__ float g_eP[NJ];          // exp(+beta * id_j)
__device__ float g_eM[NJ];          // exp(-beta * id_j)

// -------------------- f32x2 packed-FMA helpers (sm_103a) ---------------------
__device__ __forceinline__ unsigned long long pk2(float x) {
    unsigned long long r;
    asm("mov.b64 %0, {%1, %2};" : "=l"(r) : "f"(x), "f"(x));
    return r;
}
__device__ __forceinline__ void fma2(unsigned long long& d, unsigned long long a,
                                     unsigned long long b) {
    asm("fma.rn.f32x2 %0, %1, %2, %0;" : "+l"(d) : "l"(a), "l"(b));
}
__device__ __forceinline__ void upk2(unsigned long long v, float& lo, float& hi) {
    asm("mov.b64 {%0, %1}, %2;" : "=f"(lo), "=f"(hi) : "l"(v));
}

// ========== 1) prep: sort enh/inh (active rows), positions, exp tables =======
__global__ __launch_bounds__(1024) void k_prep(const float* __restrict__ ident,
                                               const float* __restrict__ enh,
                                               const float* __restrict__ inh,
                                               const float* __restrict__ beta) {
    __shared__ float sv[1024];
    __shared__ int   si[1024];
    int tid = threadIdx.x;
    float b = beta[0];

    for (int m = 0; m < 2; ++m) {
        const float* src = m ? inh : enh;
        if (tid < NA) {
            int k = (tid < NI) ? tid : tid + NO;   // skip masked rows [64,128)
            sv[tid] = src[k];
            si[tid] = k;
        } else {
            sv[tid] = 3.0e38f;
            si[tid] = -1;
        }
        __syncthreads();

        // bitonic sort ascending over 1024 slots
        for (int sz = 2; sz <= 1024; sz <<= 1) {
            for (int st = sz >> 1; st > 0; st >>= 1) {
                int ixj = tid ^ st;
                if (ixj > tid) {
                    bool up = ((tid & sz) == 0);
                    float a0 = sv[tid], a1 = sv[ixj];
                    if (up ? (a0 > a1) : (a0 < a1)) {
                        sv[tid] = a1; sv[ixj] = a0;
                        int t = si[tid]; si[tid] = si[ixj]; si[ixj] = t;
                    }
                }
                __syncthreads();
            }
        }

        if (tid < NA) {
            float v = sv[tid];
            g_cp[m][tid] = expf(b * v);
            g_cm[m][tid] = expf(-b * v);
            g_gx[m][tid] = si[tid];
        }
        if (tid < NJ) {
            float id = ident[NI + tid];
            int lo = 0, hi = NA;
            while (lo < hi) {
                int mid = (lo + hi) >> 1;
                if (sv[mid] <= id) lo = mid + 1; else hi = mid;
            }
            g_pos[m][tid] = lo;
            if (m == 0) { g_eP[tid] = expf(b * id); g_eM[tid] = expf(-b * id); }
        }
        __syncthreads();
    }
}

// ========== 2) fused warmup: 25 steps + c0, single block, O(N) per step ======
// Dual inclusive scan of (w,u) across 1024 threads (zeros beyond NA).
#define SCAN2(wv, uv)                                                          \
    {                                                                          \
        float _w = (wv), _u = (uv);                                            \
        _Pragma("unroll")                                                      \
        for (int off = 1; off < 32; off <<= 1) {                               \
            float tw = __shfl_up_sync(0xffffffffu, _w, off);                   \
            float tu = __shfl_up_sync(0xffffffffu, _u, off);                   \
            if (lane >= off) { _w += tw; _u += tu; }                           \
        }                                                                      \
        if (lane == 31) { wsc[0][wid] = _w; wsc[1][wid] = _u; }                \
        __syncthreads();                                                       \
        if (wid == 0) {                                                        \
            float a = wsc[0][lane], c = wsc[1][lane];                          \
            _Pragma("unroll")                                                  \
            for (int off = 1; off < 32; off <<= 1) {                           \
                float ta = __shfl_up_sync(0xffffffffu, a, off);                \
                float tc = __shfl_up_sync(0xffffffffu, c, off);                \
                if (lane >= off) { a += ta; c += tc; }                         \
            }                                                                  \
            wsc[0][lane] = a; wsc[1][lane] = c;                                \
        }                                                                      \
        __syncthreads();                                                       \
        float offW = wid ? wsc[0][wid - 1] : 0.f;                              \
        float offU = wid ? wsc[1][wid - 1] : 0.f;                              \
        if (tid < NA) { W[tid] = _w + offW; U[tid] = _u + offU; }              \
        if (tid == 1023) { sh_tot[0] = _w + offW; sh_tot[1] = _u + offU; }     \
        __syncthreads();                                                       \
    }

__global__ __launch_bounds__(1024) void k_warm(const float* __restrict__ delta) {
    __shared__ float cp0[NA], cm0[NA], cp1[NA], cm1[NA];
    __shared__ float eP[NJ], eM[NJ];
    __shared__ short gx0[NA], gx1[NA], ps0[NJ], ps1[NJ];
    __shared__ float conc[NT];
    __shared__ float W[NA], U[NA];
    __shared__ float wsc[2][32];
    __shared__ float red[32];
    __shared__ float sh_tot[2];
    __shared__ float sh_inv;

    int tid = threadIdx.x, lane = tid & 31, wid = tid >> 5;
    float dsc = delta[0] * INVN;

    if (tid < NA) {
        cp0[tid] = g_cp[0][tid]; cm0[tid] = g_cm[0][tid];
        cp1[tid] = g_cp[1][tid]; cm1[tid] = g_cm[1][tid];
        gx0[tid] = (short)g_gx[0][tid]; gx1[tid] = (short)g_gx[1][tid];
        ps0[tid] = (short)g_pos[0][tid]; ps1[tid] = (short)g_pos[1][tid];
        eP[tid]  = g_eP[tid]; eM[tid] = g_eM[tid];
    }
    conc[tid] = INVN;
    __syncthreads();

    for (int it = 0; it <= WARM; ++it) {
        bool c0pass = (it == WARM);
        // ---- enhancer half ----
        float w = 0.f, u = 0.f;
        if (tid < NA) {
            int k = gx0[tid];
            float cv = (c0pass && k < NI) ? 0.f : conc[k];
            w = cv * cp0[tid]; u = cv * cm0[tid];
        }
        SCAN2(w, u);
        float Ej = 0.f;
        if (tid < NJ) {
            int p = ps0[tid];
            float pre = p ? W[p - 1] : 0.f;
            float suf = sh_tot[1] - (p ? U[p - 1] : 0.f);
            Ej = eM[tid] * pre + eP[tid] * suf;
        }
        __syncthreads();                // protect W,U before reuse
        // ---- inhibitor half ----
        w = 0.f; u = 0.f;
        if (tid < NA) {
            int k = gx1[tid];
            float cv = (c0pass && k < NI) ? 0.f : conc[k];
            w = cv * cp1[tid]; u = cv * cm1[tid];
        }
        SCAN2(w, u);
        float nv = 0.f;
        if (tid < NJ) {
            int p = ps1[tid];
            float pre = p ? W[p - 1] : 0.f;
            float suf = sh_tot[1] - (p ? U[p - 1] : 0.f);
            float Ij = eM[tid] * pre + eP[tid] * suf;
            float dc = dsc * (Ej - Ij);
            if (c0pass) {
                g_c0[tid] = conc[NI + tid] + dc;    // no relu / no normalize
            } else {
                nv = fmaxf(conc[NI + tid] + dc, 0.f);
            }
        }
        if (c0pass) break;
        // ---- deterministic block sum + normalize ----
        float r = nv;
        #pragma unroll
        for (int off = 16; off > 0; off >>= 1)
            r += __shfl_xor_sync(0xffffffffu, r, off);
        if (lane == 0) red[wid] = r;
        __syncthreads();
        if (tid == 0) {
            float s = 0.f;
            #pragma unroll
            for (int q = 0; q < 32; ++q) s += red[q];
            sh_inv = (s > 0.f) ? 1.f / s : 1.f;
        }
        __syncthreads();
        if (tid < NJ) conc[NI + tid] = nv * sh_inv;
        __syncthreads();
    }
}

// ========== 3) batch-GEMM weights (rows k<64 only) ===========================
__global__ void k_wp(const float* __restrict__ ident, const float* __restrict__ enh,
                     const float* __restrict__ inh, const float* __restrict__ beta,
                     const float* __restrict__ delta) {
    int idx = blockIdx.x * 256 + threadIdx.x;
    if (idx >= NI * NJ) return;
    int k = idx / NJ, j = idx % NJ;
    float b = beta[0], id = ident[NI + j];
    float v = expf(-b * fabsf(enh[k] - id)) - expf(-b * fabsf(inh[k] - id));
    g_Wp[k * NJ + j] = v * (delta[0] * INVN);
}

// ========== 4) fused batch step ==============================================
// Per row b: t_j = relu(c0[j] + inputs[b,:64] @ Wp[:, j]);  s = sum_j t_j;
// out[b, 0..63] = t_{64..127} * (s>0 ? 1/s : 1)
__global__ __launch_bounds__(256) void k_batch(const float* __restrict__ in,
                                               float* __restrict__ out) {
    __shared__ __align__(16) float Vs[64][68];   // [k][m], padded
    __shared__ __align__(16) float Ws[64][64];   // [k][jloc]
    __shared__ float c0s[64];

    int tid = threadIdx.x;
    int m0  = blockIdx.x * 64;

    for (int r = tid; r < 64 * 64; r += 256) {
        int m = r >> 6, k = r & 63;
        Vs[k][m] = in[(m0 + m) * 64 + k];
    }

    int ty = tid >> 4, tx = tid & 15;
    float rsum[4] = {0.f, 0.f, 0.f, 0.f};
    float outv[16];

    for (int jt = 0; jt < 15; ++jt) {
        __syncthreads();
        for (int r = tid; r < 64 * 64; r += 256) {
            int k = r >> 6, l = r & 63;
            Ws[k][l] = g_Wp[k * NJ + jt * 64 + l];
        }
        if (tid < 64) c0s[tid] = g_c0[jt * 64 + tid];
        __syncthreads();

        unsigned long long acc[8];
        #pragma unroll
        for (int u = 0; u < 8; ++u) acc[u] = 0ull;

        #pragma unroll 8
        for (int k = 0; k < 64; ++k) {
            float4 rv = *(const float4*)&Vs[k][ty * 4];
            const unsigned long long* wp =
                (const unsigned long long*)&Ws[k][tx * 4];
            unsigned long long w01 = wp[0], w23 = wp[1];
            unsigned long long v;
            v = pk2(rv.x); fma2(acc[0], v, w01); fma2(acc[1], v, w23);
            v = pk2(rv.y); fma2(acc[2], v, w01); fma2(acc[3], v, w23);
            v = pk2(rv.z); fma2(acc[4], v, w01); fma2(acc[5], v, w23);
            v = pk2(rv.w); fma2(acc[6], v, w01); fma2(acc[7], v, w23);
        }

        #pragma unroll
        for (int i = 0; i < 4; ++i) {
            #pragma unroll
            for (int u2 = 0; u2 < 2; ++u2) {
                float a0, a1;
                upk2(acc[i * 2 + u2], a0, a1);
                int c = tx * 4 + u2 * 2;
                float t0 = fmaxf(c0s[c]     + a0, 0.f);
                float t1 = fmaxf(c0s[c + 1] + a1, 0.f);
                rsum[i] += t0 + t1;
                if (jt == 0) {
                    outv[i * 4 + u2 * 2]     = t0;
                    outv[i * 4 + u2 * 2 + 1] = t1;
                }
            }
        }
    }

    #pragma unroll
    for (int i = 0; i < 4; ++i) {
        #pragma unroll
        for (int off = 8; off > 0; off >>= 1)
            rsum[i] += __shfl_xor_sync(0xffffffffu, rsum[i], off);
    }

    #pragma unroll
    for (int i = 0; i < 4; ++i) {
        float s   = rsum[i];
        float inv = (s > 0.f) ? 1.f / s : 1.f;
        int b = m0 + ty * 4 + i;
        float4 o;
        o.x = outv[i * 4 + 0] * inv;
        o.y = outv[i * 4 + 1] * inv;
        o.z = outv[i * 4 + 2] * inv;
        o.w = outv[i * 4 + 3] * inv;
        *(float4*)&out[b * 64 + tx * 4] = o;
    }
}

// -------------------- launch -------------------------------------------------
extern "C" void kernel_launch(void* const* d_in, const int* in_sizes, int n_in,
                              void* d_out, int out_size) {
    const float* inputs = (const float*)d_in[0];
    const float* ident  = (const float*)d_in[1];
    const float* enh    = (const float*)d_in[2];
    const float* inh    = (const float*)d_in[3];
    const float* beta   = (const float*)d_in[4];
    const float* delta  = (const float*)d_in[5];
    float* out = (float*)d_out;
    int B = in_sizes[0] / NI;   // 16384

    k_wp<<<(NI * NJ + 255) / 256, 256>>>(ident, enh, inh, beta, delta);
    k_prep<<<1, 1024>>>(ident, enh, inh, beta);
    k_warm<<<1, 1024>>>(delta);
    k_batch<<<B / 64, 256>>>(inputs, out);
}

// round 3
// speedup vs baseline: 6.4725x; 1.2556x over previous
#include <cuda_runtime.h>

// Problem constants (fixed by the reference)
#define NT   1024          // N = I + O + R
#define NI   64            // I
#define NO   64            // O
#define NJ   960           // columns 64..1023 (the only ones ever needed)
#define NA   960           // active rows: k<64 or 128<=k<1024
#define WARM 25
#define INVN (1.0f/1024.0f)

typedef unsigned long long u64;

// -------------------- device scratch (no allocations allowed) ----------------
__device__ float g_Wp[NI * NJ];   // (delta/N) * sig_diff[k<64][j]  (pre-scaled)
__device__ float g_c0[NJ];        // warm-state constant offset for the batch step
__device__ float g_srt[2][NA];    // sorted enhancer / inhibitor values (active rows)
__device__ int   g_gxr[2][NA];    // original conc index k for each sorted slot

// -------------------- f32x2 packed-FMA helpers (sm_103a) ---------------------
__device__ __forceinline__ u64 pk2(float x) {
    u64 r; asm("mov.b64 %0, {%1, %2};" : "=l"(r) : "f"(x), "f"(x)); return r;
}
__device__ __forceinline__ void fma2(u64& d, u64 a, u64 b) {
    asm("fma.rn.f32x2 %0, %1, %2, %0;" : "+l"(d) : "l"(a), "l"(b));
}
__device__ __forceinline__ void upk2(u64 v, float& lo, float& hi) {
    asm("mov.b64 {%0, %1}, %2;" : "=f"(lo), "=f"(hi) : "l"(v));
}

// ========== 1) prep: parallel counting-rank sort of enh/inh active rows ======
// 32 blocks: block b handles stream m=b&1, chunk c=b>>1 (60 elements each).
// rank(e) = #{j: v_j < v_e or (v_j==v_e and j<e)}; scatter value+index to g_srt.
__global__ __launch_bounds__(1024) void k_prep(const float* __restrict__ enh,
                                               const float* __restrict__ inh) {
    __shared__ float sv[NA];
    int m = blockIdx.x & 1;
    int chunk = blockIdx.x >> 1;
    const float* src = m ? inh : enh;
    int tid = threadIdx.x;

    for (int t = tid; t < NA; t += 1024) {
        int k = (t < NI) ? t : t + NO;
        sv[t] = src[k];
    }
    __syncthreads();

    int el = tid >> 4;          // 0..63 (60 used)
    int jp = tid & 15;          // 16 partials per element
    if (el < 60) {
        int e = chunk * 60 + el;
        float v = sv[e];
        int rank = 0;
        int j0 = jp * 60;
        #pragma unroll 4
        for (int jj = 0; jj < 60; ++jj) {
            int j = j0 + jj;
            float o = sv[j];
            rank += (o < v) || (o == v && j < e);
        }
        #pragma unroll
        for (int off = 1; off < 16; off <<= 1)
            rank += __shfl_xor_sync(0xffffffffu, rank, off);
        if (jp == 0) {
            g_srt[m][rank] = v;
            g_gxr[m][rank] = (e < NI) ? e : e + NO;
        }
    }
}

// ========== 2) fused warmup: 25 steps + c0, 128 threads, O(N) per step =======
// Warp w handles one of 4 scan streams: (enh:w, enh:u, inh:w, inh:u).
__global__ __launch_bounds__(128) void k_warm(const float* __restrict__ ident,
                                              const float* __restrict__ beta,
                                              const float* __restrict__ delta) {
    __shared__ float tbl[4][NA];     // 0:exp(+b*eS) 1:exp(-b*eS) 2:exp(+b*iS) 3:exp(-b*iS)
    __shared__ short gxs[2][NA];
    __shared__ short pss[2][NA];
    __shared__ float eP[NA], eM[NA];
    __shared__ float srt0[NA], srt1[NA];
    __shared__ float conc[NT];
    __shared__ float P[4][NA];
    __shared__ float tot[4];
    __shared__ float red[4];

    int tid = threadIdx.x, lane = tid & 31, w = tid >> 5;
    float b = beta[0];
    float dsc = delta[0] * INVN;

    for (int i = tid; i < NA; i += 128) {
        float v0 = g_srt[0][i], v1 = g_srt[1][i];
        srt0[i] = v0; srt1[i] = v1;
        tbl[0][i] = expf(b * v0);  tbl[1][i] = expf(-b * v0);
        tbl[2][i] = expf(b * v1);  tbl[3][i] = expf(-b * v1);
        gxs[0][i] = (short)g_gxr[0][i];
        gxs[1][i] = (short)g_gxr[1][i];
        float id = ident[NI + i];
        eP[i] = expf(b * id); eM[i] = expf(-b * id);
    }
    for (int i = tid; i < NT; i += 128) conc[i] = INVN;
    __syncthreads();

    // positions: #{sorted <= id_j}
    for (int i = tid; i < NA; i += 128) {
        float id = ident[NI + i];
        int lo = 0, hi = NA;
        while (lo < hi) { int mid = (lo + hi) >> 1; if (srt0[mid] <= id) lo = mid + 1; else hi = mid; }
        pss[0][i] = (short)lo;
        lo = 0; hi = NA;
        while (lo < hi) { int mid = (lo + hi) >> 1; if (srt1[mid] <= id) lo = mid + 1; else hi = mid; }
        pss[1][i] = (short)lo;
    }
    __syncthreads();

    int ms = w >> 1;     // gather-index stream for this warp
    for (int it = 0; it <= WARM; ++it) {
        bool cp = (it == WARM);
        // ---- per-warp scan of one stream (30 elems/lane in registers) ----
        float loc[30];
        float run = 0.f;
        int base = lane * 30;
        #pragma unroll
        for (int i = 0; i < 30; ++i) {
            int k = gxs[ms][base + i];
            float cv = conc[k];
            if (cp && k < NI) cv = 0.f;
            run += cv * tbl[w][base + i];
            loc[i] = run;
        }
        float v = run;
        #pragma unroll
        for (int off = 1; off < 32; off <<= 1) {
            float t = __shfl_up_sync(0xffffffffu, v, off);
            if (lane >= off) v += t;
        }
        float excl = v - run;
        #pragma unroll
        for (int i = 0; i < 30; ++i) P[w][base + i] = loc[i] + excl;
        if (lane == 31) tot[w] = v;
        __syncthreads();

        // ---- outputs: 960 across 128 threads ----
        float nv[8];
        float lsum = 0.f;
        #pragma unroll
        for (int ii = 0; ii < 8; ++ii) {
            int j = tid + ii * 128;
            nv[ii] = 0.f;
            if (j < NA) {
                int pA = pss[0][j], pB = pss[1][j];
                float preA = pA ? P[0][pA - 1] : 0.f;
                float sufA = tot[1] - (pA ? P[1][pA - 1] : 0.f);
                float E = eM[j] * preA + eP[j] * sufA;
                float preB = pB ? P[2][pB - 1] : 0.f;
                float sufB = tot[3] - (pB ? P[3][pB - 1] : 0.f);
                float I = eM[j] * preB + eP[j] * sufB;
                float dc = dsc * (E - I);
                if (cp) {
                    g_c0[j] = conc[NI + j] + dc;     // no relu / no normalize
                } else {
                    nv[ii] = fmaxf(conc[NI + j] + dc, 0.f);
                    lsum += nv[ii];
                }
            }
        }
        if (cp) break;
        // ---- deterministic sum + normalize ----
        #pragma unroll
        for (int off = 16; off > 0; off >>= 1)
            lsum += __shfl_xor_sync(0xffffffffu, lsum, off);
        if (lane == 0) red[w] = lsum;
        __syncthreads();
        float s = red[0] + red[1] + red[2] + red[3];
        float inv = (s > 0.f) ? 1.f / s : 1.f;
        #pragma unroll
        for (int ii = 0; ii < 8; ++ii) {
            int j = tid + ii * 128;
            if (j < NA) conc[NI + j] = nv[ii] * inv;
        }
        __syncthreads();
    }
}

// ========== 3) batch-GEMM weights (rows k<64 only) ===========================
__global__ void k_wp(const float* __restrict__ ident, const float* __restrict__ enh,
                     const float* __restrict__ inh, const float* __restrict__ beta,
                     const float* __restrict__ delta) {
    int idx = blockIdx.x * 256 + threadIdx.x;
    if (idx >= NI * NJ) return;
    int k = idx / NJ, j = idx - k * NJ;
    float b = beta[0], id = ident[NI + j];
    float v = expf(-b * fabsf(enh[k] - id)) - expf(-b * fabsf(inh[k] - id));
    g_Wp[k * NJ + j] = v * (delta[0] * INVN);
}

// ========== 4) fused batch step ==============================================
// Block: 64 rows x 960 cols (5 tiles of 192). 256 threads = 16(ty) x 16(tx),
// micro-tile 4 rows x 12 cols, f32x2 col pairs, rows pre-duplicated in smem.
// smem layout (bytes):
//   Vs2  u64 [64*66]     @      0  (33792)
//   Ws   f32 [64*192]    @  33792  (49152)
//   Ts   f32 [64*64]     @  82944  (16384)   unnormalized t for cols 0..63
//   c0s  f32 [192]       @  99328  (  768)
//   sinv f32 [64]        @ 100096  (  256)
#define SMB 100352
__global__ __launch_bounds__(256, 2) void k_batch(const float* __restrict__ in,
                                                  float* __restrict__ out) {
    extern __shared__ __align__(16) char sm_[];
    u64*   Vs2  = (u64*)sm_;
    float* Ws   = (float*)(sm_ + 33792);
    float* Ts   = (float*)(sm_ + 82944);
    float* c0s  = (float*)(sm_ + 99328);
    float* sinv = (float*)(sm_ + 100096);

    int tid = threadIdx.x;
    int m0  = blockIdx.x * 64;
    int ty = tid >> 4, tx = tid & 15;

    // stage rows, duplicated as f32x2 pairs: Vs2[k*66 + m] = {v,v}
    for (int idx = tid; idx < 64 * 64; idx += 256) {
        int m = idx >> 6, k = idx & 63;          // lanes: consecutive k -> coalesced
        float v = in[(m0 + m) * 64 + k];
        Vs2[k * 66 + m] = pk2(v);
    }

    float rsum[4] = {0.f, 0.f, 0.f, 0.f};

    for (int jt = 0; jt < 5; ++jt) {
        __syncthreads();
        for (int idx = tid; idx < 64 * 192; idx += 256) {
            int k = idx / 192, l = idx - k * 192;
            Ws[k * 192 + l] = g_Wp[k * NJ + jt * 192 + l];
        }
        if (tid < 192) c0s[tid] = g_c0[jt * 192 + tid];
        __syncthreads();

        u64 acc[4][6];
        #pragma unroll
        for (int i = 0; i < 4; ++i)
            #pragma unroll
            for (int c = 0; c < 6; ++c) acc[i][c] = 0ull;

        const u64* vp = Vs2 + ty * 4;
        const u64* wq = (const u64*)Ws + tx * 6;

        #pragma unroll 8
        for (int k = 0; k < 64; ++k) {
            u64 r0 = vp[k * 66 + 0], r1 = vp[k * 66 + 1];
            u64 r2 = vp[k * 66 + 2], r3 = vp[k * 66 + 3];
            u64 w0 = wq[k * 96 + 0], w1 = wq[k * 96 + 1], w2 = wq[k * 96 + 2];
            u64 w3 = wq[k * 96 + 3], w4 = wq[k * 96 + 4], w5 = wq[k * 96 + 5];
            fma2(acc[0][0], r0, w0); fma2(acc[0][1], r0, w1); fma2(acc[0][2], r0, w2);
            fma2(acc[0][3], r0, w3); fma2(acc[0][4], r0, w4); fma2(acc[0][5], r0, w5);
            fma2(acc[1][0], r1, w0); fma2(acc[1][1], r1, w1); fma2(acc[1][2], r1, w2);
            fma2(acc[1][3], r1, w3); fma2(acc[1][4], r1, w4); fma2(acc[1][5], r1, w5);
            fma2(acc[2][0], r2, w0); fma2(acc[2][1], r2, w1); fma2(acc[2][2], r2, w2);
            fma2(acc[2][3], r2, w3); fma2(acc[2][4], r2, w4); fma2(acc[2][5], r2, w5);
            fma2(acc[3][0], r3, w0); fma2(acc[3][1], r3, w1); fma2(acc[3][2], r3, w2);
            fma2(acc[3][3], r3, w3); fma2(acc[3][4], r3, w4); fma2(acc[3][5], r3, w5);
        }

        #pragma unroll
        for (int i = 0; i < 4; ++i) {
            #pragma unroll
            for (int c = 0; c < 6; ++c) {
                float a0, a1; upk2(acc[i][c], a0, a1);
                int col = tx * 12 + c * 2;
                float t0 = fmaxf(c0s[col]     + a0, 0.f);
                float t1 = fmaxf(c0s[col + 1] + a1, 0.f);
                rsum[i] += t0 + t1;
                if (jt == 0 && col < 64) {
                    Ts[(ty * 4 + i) * 64 + col]     = t0;
                    Ts[(ty * 4 + i) * 64 + col + 1] = t1;
                }
            }
        }
    }

    // reduce row sums across the 16 tx lanes
    #pragma unroll
    for (int i = 0; i < 4; ++i) {
        #pragma unroll
        for (int off = 1; off < 16; off <<= 1)
            rsum[i] += __shfl_xor_sync(0xffffffffu, rsum[i], off);
    }
    if (tx == 0) {
        #pragma unroll
        for (int i = 0; i < 4; ++i) {
            float s = rsum[i];
            sinv[ty * 4 + i] = (s > 0.f) ? 1.f / s : 1.f;
        }
    }
    __syncthreads();

    // scale + store: thread -> row tid>>2, 16 cols
    int r  = tid >> 2;
    int cq = (tid & 3) * 16;
    float inv = sinv[r];
    #pragma unroll
    for (int q = 0; q < 4; ++q) {
        float4 t = *(const float4*)&Ts[r * 64 + cq + q * 4];
        t.x *= inv; t.y *= inv; t.z *= inv; t.w *= inv;
        *(float4*)&out[(m0 + r) * 64 + cq + q * 4] = t;
    }
}

// -------------------- launch -------------------------------------------------
extern "C" void kernel_launch(void* const* d_in, const int* in_sizes, int n_in,
                              void* d_out, int out_size) {
    const float* inputs = (const float*)d_in[0];
    const float* ident  = (const float*)d_in[1];
    const float* enh    = (const float*)d_in[2];
    const float* inh    = (const float*)d_in[3];
    const float* beta   = (const float*)d_in[4];
    const float* delta  = (const float*)d_in[5];
    float* out = (float*)d_out;
    int B = in_sizes[0] / NI;   // 16384

    static int smset = 0;
    if (!smset) {
        cudaFuncSetAttribute(k_batch, cudaFuncAttributeMaxDynamicSharedMemorySize, SMB);
        smset = 1;
    }

    k_wp<<<(NI * NJ + 255) / 256, 256>>>(ident, enh, inh, beta, delta);
    k_prep<<<32, 1024>>>(enh, inh);
    k_warm<<<1, 128>>>(ident, beta, delta);
    k_batch<<<B / 64, 256, SMB>>>(inputs, out);
}

// round 5
// speedup vs baseline: 10.4027x; 1.6072x over previous
#include <cuda_runtime.h>
#include <cuda_bf16.h>
#include <cstdint>

// Problem constants (fixed by the reference)
#define NT   1024
#define NI   64
#define NO   64
#define NJ   960
#define NA   960
#define WARM 25
#define INVN (1.0f/1024.0f)

typedef unsigned long long u64;
typedef unsigned int u32;

// -------------------- device scratch (no allocations allowed) ----------------
__device__ float g_c0[NJ];        // warm-state constant offset for the batch step
__device__ float g_srt[2][NA];    // sorted enhancer / inhibitor values
__device__ int   g_gxr[2][NA];    // original conc index per sorted slot
// W in mma B-fragment layout: [tile(120)][kstep(4)][lane(32)] = uint4
//   .x = bf16x2 hi {W[k0],W[k0+1]}, .y = hi {W[k0+8],W[k0+9]}, .z/.w = lo same
__device__ __align__(16) uint4 g_Wf[120 * 4 * 32];

// -------------------- helpers ------------------------------------------------
__device__ __forceinline__ u32 smem_u32(const void* p) {
    u32 a;
    asm("{ .reg .u64 t; cvta.to.shared.u64 t, %1; cvt.u32.u64 %0, t; }"
        : "=r"(a) : "l"(p));
    return a;
}
__device__ __forceinline__ void cpa16(u32 dst, const void* src) {
    asm volatile("cp.async.cg.shared.global [%0], [%1], 16;" :: "r"(dst), "l"(src));
}
__device__ __forceinline__ void ldmx4(u32* r, u32 addr) {
    asm volatile("ldmatrix.sync.aligned.m8n8.x4.shared.b16 {%0,%1,%2,%3}, [%4];"
        : "=r"(r[0]), "=r"(r[1]), "=r"(r[2]), "=r"(r[3]) : "r"(addr));
}
__device__ __forceinline__ void mma_bf16(float& d0, float& d1, float& d2, float& d3,
                                         const u32* a, u32 b0, u32 b1) {
    asm volatile("mma.sync.aligned.m16n8k16.row.col.f32.bf16.bf16.f32 "
        "{%0,%1,%2,%3}, {%4,%5,%6,%7}, {%8,%9}, {%0,%1,%2,%3};"
        : "+f"(d0), "+f"(d1), "+f"(d2), "+f"(d3)
        : "r"(a[0]), "r"(a[1]), "r"(a[2]), "r"(a[3]), "r"(b0), "r"(b1));
}
#define SWZ(o) ((o) ^ (((o) >> 3) & 0x70))

// pack two floats as bf16x2 hi word + bf16x2 lo word (low half = first arg)
__device__ __forceinline__ void split2(float a, float b, u32& h, u32& l) {
    __nv_bfloat16 ha = __float2bfloat16(a), hb = __float2bfloat16(b);
    __nv_bfloat16 la = __float2bfloat16(a - __bfloat162float(ha));
    __nv_bfloat16 lb = __float2bfloat16(b - __bfloat162float(hb));
    __nv_bfloat162 hh = __halves2bfloat162(ha, hb);
    __nv_bfloat162 ll = __halves2bfloat162(la, lb);
    h = *(u32*)&hh;  l = *(u32*)&ll;
}

// ========== 1) prep: parallel counting-rank sort of enh/inh active rows ======
__global__ __launch_bounds__(1024) void k_prep(const float* __restrict__ enh,
                                               const float* __restrict__ inh) {
    __shared__ float sv[NA];
    int m = blockIdx.x & 1;
    int chunk = blockIdx.x >> 1;
    const float* src = m ? inh : enh;
    int tid = threadIdx.x;

    for (int t = tid; t < NA; t += 1024) {
        int k = (t < NI) ? t : t + NO;
        sv[t] = src[k];
    }
    __syncthreads();

    int el = tid >> 4, jp = tid & 15;
    if (el < 60) {
        int e = chunk * 60 + el;
        float v = sv[e];
        int rank = 0;
        int j0 = jp * 60;
        #pragma unroll 4
        for (int jj = 0; jj < 60; ++jj) {
            int j = j0 + jj;
            float o = sv[j];
            rank += (o < v) || (o == v && j < e);
        }
        #pragma unroll
        for (int off = 1; off < 16; off <<= 1)
            rank += __shfl_xor_sync(0xffffffffu, rank, off);
        if (jp == 0) {
            g_srt[m][rank] = v;
            g_gxr[m][rank] = (e < NI) ? e : e + NO;
        }
    }
}

// ========== 2) fused warmup: 25 steps + c0, 128 threads, O(N) per step =======
__global__ __launch_bounds__(128) void k_warm(const float* __restrict__ ident,
                                              const float* __restrict__ beta,
                                              const float* __restrict__ delta) {
    __shared__ float tbl[4][NA];
    __shared__ short gxs[2][NA];
    __shared__ short pss[2][NA];
    __shared__ float eP[NA], eM[NA];
    __shared__ float srt0[NA], srt1[NA];
    __shared__ float conc[NT];
    __shared__ float P[4][NA];
    __shared__ float tot[4];
    __shared__ float red[4];

    int tid = threadIdx.x, lane = tid & 31, w = tid >> 5;
    float b = beta[0];
    float dsc = delta[0] * INVN;

    for (int i = tid; i < NA; i += 128) {
        float v0 = g_srt[0][i], v1 = g_srt[1][i];
        srt0[i] = v0; srt1[i] = v1;
        tbl[0][i] = expf(b * v0);  tbl[1][i] = expf(-b * v0);
        tbl[2][i] = expf(b * v1);  tbl[3][i] = expf(-b * v1);
        gxs[0][i] = (short)g_gxr[0][i];
        gxs[1][i] = (short)g_gxr[1][i];
        float id = ident[NI + i];
        eP[i] = expf(b * id); eM[i] = expf(-b * id);
    }
    for (int i = tid; i < NT; i += 128) conc[i] = INVN;
    __syncthreads();

    for (int i = tid; i < NA; i += 128) {
        float id = ident[NI + i];
        int lo = 0, hi = NA;
        while (lo < hi) { int mid = (lo + hi) >> 1; if (srt0[mid] <= id) lo = mid + 1; else hi = mid; }
        pss[0][i] = (short)lo;
        lo = 0; hi = NA;
        while (lo < hi) { int mid = (lo + hi) >> 1; if (srt1[mid] <= id) lo = mid + 1; else hi = mid; }
        pss[1][i] = (short)lo;
    }
    __syncthreads();

    int ms = w >> 1;
    for (int it = 0; it <= WARM; ++it) {
        bool cp = (it == WARM);
        float loc[30];
        float run = 0.f;
        int base = lane * 30;
        #pragma unroll
        for (int i = 0; i < 30; ++i) {
            int k = gxs[ms][base + i];
            float cv = conc[k];
            if (cp && k < NI) cv = 0.f;
            run += cv * tbl[w][base + i];
            loc[i] = run;
        }
        float v = run;
        #pragma unroll
        for (int off = 1; off < 32; off <<= 1) {
            float t = __shfl_up_sync(0xffffffffu, v, off);
            if (lane >= off) v += t;
        }
        float excl = v - run;
        #pragma unroll
        for (int i = 0; i < 30; ++i) P[w][base + i] = loc[i] + excl;
        if (lane == 31) tot[w] = v;
        __syncthreads();

        float nv[8];
        float lsum = 0.f;
        #pragma unroll
        for (int ii = 0; ii < 8; ++ii) {
            int j = tid + ii * 128;
            nv[ii] = 0.f;
            if (j < NA) {
                int pA = pss[0][j], pB = pss[1][j];
                float preA = pA ? P[0][pA - 1] : 0.f;
                float sufA = tot[1] - (pA ? P[1][pA - 1] : 0.f);
                float E = eM[j] * preA + eP[j] * sufA;
                float preB = pB ? P[2][pB - 1] : 0.f;
                float sufB = tot[3] - (pB ? P[3][pB - 1] : 0.f);
                float I = eM[j] * preB + eP[j] * sufB;
                float dc = dsc * (E - I);
                if (cp) {
                    g_c0[j] = conc[NI + j] + dc;
                } else {
                    nv[ii] = fmaxf(conc[NI + j] + dc, 0.f);
                    lsum += nv[ii];
                }
            }
        }
        if (cp) break;
        #pragma unroll
        for (int off = 16; off > 0; off >>= 1)
            lsum += __shfl_xor_sync(0xffffffffu, lsum, off);
        if (lane == 0) red[w] = lsum;
        __syncthreads();
        float s = red[0] + red[1] + red[2] + red[3];
        float inv = (s > 0.f) ? 1.f / s : 1.f;
        #pragma unroll
        for (int ii = 0; ii < 8; ++ii) {
            int j = tid + ii * 128;
            if (j < NA) conc[NI + j] = nv[ii] * inv;
        }
        __syncthreads();
    }
}

// ========== 3) weights straight into mma B-fragment layout ===================
__global__ void k_wp(const float* __restrict__ ident, const float* __restrict__ enh,
                     const float* __restrict__ inh, const float* __restrict__ beta,
                     const float* __restrict__ delta) {
    int idx = blockIdx.x * 256 + threadIdx.x;
    if (idx >= 120 * 4 * 32) return;
    int lane = idx & 31;
    int ts = idx >> 5;
    int t = ts >> 2, s = ts & 3;
    int j = t * 8 + (lane >> 2);           // column 0..959
    int k0 = s * 16 + (lane & 3) * 2;      // k row base
    float b = beta[0], dsc = delta[0] * INVN;
    float id = ident[NI + j];

    float wv[4];
    int ks[4] = {k0, k0 + 1, k0 + 8, k0 + 9};
    #pragma unroll
    for (int i = 0; i < 4; ++i) {
        int k = ks[i];
        wv[i] = (expf(-b * fabsf(enh[k] - id)) - expf(-b * fabsf(inh[k] - id))) * dsc;
    }
    uint4 o;
    split2(wv[0], wv[1], o.x, o.z);
    split2(wv[2], wv[3], o.y, o.w);
    g_Wf[idx] = o;
}

// ========== 4) mma.sync fused batch step =====================================
// grid 128 x 256 thr. Warp (wid>>1 = warpM, wid&1 = warpN): 32 rows x 480 cols.
// 4 chunks of 30 n8-tiles, cp.async double-buffered.
#define CH    30
#define CHB   (CH * 4 * 32 * 16)    // 61440 bytes per chunk
#define OF_AHI 0
#define OF_ALO 16384
#define OF_B   32768                 // 2 * CHB = 122880
#define OF_TS  155648                // 128*64*4 = 32768
#define OF_C0  188416                // 960*4
#define OF_SUM 192256                // 2*128*4
#define OF_SINV 193280               // 128*4
#define SMB    193792

__global__ __launch_bounds__(256) void k_batch(const float* __restrict__ in,
                                               float* __restrict__ out) {
    extern __shared__ __align__(16) char smb[];
    u32 sb = smem_u32(smb);
    float* Ts   = (float*)(smb + OF_TS);
    float* c0s  = (float*)(smb + OF_C0);
    float* sums = (float*)(smb + OF_SUM);
    float* sinv = (float*)(smb + OF_SINV);

    int tid = threadIdx.x, lane = tid & 31, wid = tid >> 5;
    int warpM = wid >> 1, warpN = wid & 1;
    int m0 = blockIdx.x * 128;

    // ---- prefetch B chunk 0 ----
    for (int i = tid; i < CHB / 16; i += 256)
        cpa16(sb + OF_B + i * 16, (const char*)g_Wf + i * 16);
    asm volatile("cp.async.commit_group;" ::: "memory");

    // ---- stage A as swizzled bf16 hi/lo ----
    for (int idx = tid; idx < 128 * 8; idx += 256) {
        int m = idx >> 3, c = idx & 7;
        const float4* p = (const float4*)(in + (size_t)(m0 + m) * 64 + c * 8);
        float4 v0 = p[0], v1 = p[1];
        uint4 H, L;
        split2(v0.x, v0.y, H.x, L.x); split2(v0.z, v0.w, H.y, L.y);
        split2(v1.x, v1.y, H.z, L.z); split2(v1.z, v1.w, H.w, L.w);
        u32 off = SWZ(m * 128 + c * 16);
        *(uint4*)(smb + OF_AHI + off) = H;
        *(uint4*)(smb + OF_ALO + off) = L;
    }
    for (int i = tid; i < NJ; i += 256) c0s[i] = g_c0[i];
    __syncthreads();

    // ---- A fragments (held in registers for the whole kernel) ----
    u32 ah[2][4][4], al[2][4][4];
    {
        int sub = lane >> 3;
        int rr = (lane & 7) + (sub & 1) * 8;
        int kb = (sub >> 1) * 16;
        #pragma unroll
        for (int mt = 0; mt < 2; ++mt)
            #pragma unroll
            for (int s = 0; s < 4; ++s) {
                u32 off = SWZ((warpM * 32 + mt * 16 + rr) * 128 + s * 32 + kb);
                ldmx4(ah[mt][s], sb + OF_AHI + off);
                ldmx4(al[mt][s], sb + OF_ALO + off);
            }
    }

    float rs[2][2] = {{0.f, 0.f}, {0.f, 0.f}};

    for (int c = 0; c < 4; ++c) {
        if (c) __syncthreads();               // compute c-1 done before reuse
        if (c < 3) {
            const char* src = (const char*)g_Wf + (size_t)(c + 1) * CHB;
            u32 dstb = sb + OF_B + ((c + 1) & 1) * CHB;
            for (int i = tid; i < CHB / 16; i += 256)
                cpa16(dstb + i * 16, src + i * 16);
            asm volatile("cp.async.commit_group;" ::: "memory");
            asm volatile("cp.async.wait_group 1;" ::: "memory");
        } else {
            asm volatile("cp.async.wait_group 0;" ::: "memory");
        }
        __syncthreads();

        const uint4* Bp = (const uint4*)(smb + OF_B + (c & 1) * CHB);
        #pragma unroll 1
        for (int nt = 0; nt < 15; ++nt) {
            int lt = warpN * 15 + nt;
            int tG = c * CH + lt;
            uint4 bf[4];
            #pragma unroll
            for (int s = 0; s < 4; ++s)
                bf[s] = Bp[(lt * 4 + s) * 32 + lane];

            int colb = tG * 8 + (lane & 3) * 2;
            float c00 = c0s[colb], c01 = c0s[colb + 1];

            #pragma unroll
            for (int mt = 0; mt < 2; ++mt) {
                float d0 = 0.f, d1 = 0.f, d2 = 0.f, d3 = 0.f;
                #pragma unroll
                for (int s = 0; s < 4; ++s) {
                    mma_bf16(d0, d1, d2, d3, ah[mt][s], bf[s].x, bf[s].y);
                    mma_bf16(d0, d1, d2, d3, al[mt][s], bf[s].x, bf[s].y);
                    mma_bf16(d0, d1, d2, d3, ah[mt][s], bf[s].z, bf[s].w);
                }
                float t0 = fmaxf(d0 + c00, 0.f), t1 = fmaxf(d1 + c01, 0.f);
                float t2 = fmaxf(d2 + c00, 0.f), t3 = fmaxf(d3 + c01, 0.f);
                rs[mt][0] += t0 + t1;
                rs[mt][1] += t2 + t3;
                if (tG < 8) {
                    int r0 = warpM * 32 + mt * 16 + (lane >> 2);
                    float2 p0 = {t0, t1}, p1 = {t2, t3};
                    *(float2*)&Ts[r0 * 64 + colb] = p0;
                    *(float2*)&Ts[(r0 + 8) * 64 + colb] = p1;
                }
            }
        }
    }

    // ---- rowsums: reduce over the 4 col-lanes of each quad ----
    #pragma unroll
    for (int mt = 0; mt < 2; ++mt)
        #pragma unroll
        for (int h = 0; h < 2; ++h) {
            rs[mt][h] += __shfl_xor_sync(0xffffffffu, rs[mt][h], 1);
            rs[mt][h] += __shfl_xor_sync(0xffffffffu, rs[mt][h], 2);
        }
    if ((lane & 3) == 0) {
        int rq = lane >> 2;
        #pragma unroll
        for (int mt = 0; mt < 2; ++mt) {
            sums[warpN * 128 + warpM * 32 + mt * 16 + rq] = rs[mt][0];
            sums[warpN * 128 + warpM * 32 + mt * 16 + 8 + rq] = rs[mt][1];
        }
    }
    __syncthreads();
    if (tid < 128) {
        float s = sums[tid] + sums[128 + tid];     // deterministic order
        sinv[tid] = (s > 0.f) ? 1.f / s : 1.f;
    }
    __syncthreads();

    // ---- normalized coalesced store ----
    for (int idx = tid; idx < 128 * 32; idx += 256) {
        int r = idx >> 5, h2 = idx & 31;
        float2 t = *(float2*)&Ts[r * 64 + h2 * 2];
        float iv = sinv[r];
        float2 o; o.x = t.x * iv; o.y = t.y * iv;
        *(float2*)(out + (size_t)(m0 + r) * 64 + h2 * 2) = o;
    }
}

// -------------------- launch -------------------------------------------------
extern "C" void kernel_launch(void* const* d_in, const int* in_sizes, int n_in,
                              void* d_out, int out_size) {
    const float* inputs = (const float*)d_in[0];
    const float* ident  = (const float*)d_in[1];
    const float* enh    = (const float*)d_in[2];
    const float* inh    = (const float*)d_in[3];
    const float* beta   = (const float*)d_in[4];
    const float* delta  = (const float*)d_in[5];
    float* out = (float*)d_out;
    int B = in_sizes[0] / NI;   // 16384

    static int smset = 0;
    if (!smset) {
        cudaFuncSetAttribute(k_batch, cudaFuncAttributeMaxDynamicSharedMemorySize, SMB);
        smset = 1;
    }

    k_wp<<<60, 256>>>(ident, enh, inh, beta, delta);
    k_prep<<<32, 1024>>>(enh, inh);
    k_warm<<<1, 128>>>(ident, beta, delta);
    k_batch<<<B / 128, 256, SMB>>>(inputs, out);
}

// round 6
// speedup vs baseline: 11.7055x; 1.1252x over previous
#include <cuda_runtime.h>
#include <cuda_bf16.h>
#include <cstdint>

// Problem constants (fixed by the reference)
#define NT   1024
#define NI   64
#define NO   64
#define NJ   960
#define NA   960
#define WARM 25
#define INVN (1.0f/1024.0f)

typedef unsigned long long u64;
typedef unsigned int u32;

// -------------------- device scratch (no allocations allowed) ----------------
__device__ float g_c0[NJ];        // warm-state constant offset for the batch step
__device__ float g_srt[2][NA];    // sorted enhancer / inhibitor values
__device__ int   g_gxr[2][NA];    // original conc index per sorted slot
// W in mma B-fragment layout: [tile(120)][kstep(4)][lane(32)] = uint4
__device__ __align__(16) uint4 g_Wf[120 * 4 * 32];

// -------------------- helpers ------------------------------------------------
__device__ __forceinline__ u32 smem_u32(const void* p) {
    u32 a;
    asm("{ .reg .u64 t; cvta.to.shared.u64 t, %1; cvt.u32.u64 %0, t; }"
        : "=r"(a) : "l"(p));
    return a;
}
__device__ __forceinline__ void cpa16(u32 dst, const void* src) {
    asm volatile("cp.async.cg.shared.global [%0], [%1], 16;" :: "r"(dst), "l"(src));
}
__device__ __forceinline__ void ldmx4(u32* r, u32 addr) {
    asm volatile("ldmatrix.sync.aligned.m8n8.x4.shared.b16 {%0,%1,%2,%3}, [%4];"
        : "=r"(r[0]), "=r"(r[1]), "=r"(r[2]), "=r"(r[3]) : "r"(addr));
}
__device__ __forceinline__ void mma_bf16(float& d0, float& d1, float& d2, float& d3,
                                         const u32* a, u32 b0, u32 b1) {
    asm volatile("mma.sync.aligned.m16n8k16.row.col.f32.bf16.bf16.f32 "
        "{%0,%1,%2,%3}, {%4,%5,%6,%7}, {%8,%9}, {%0,%1,%2,%3};"
        : "+f"(d0), "+f"(d1), "+f"(d2), "+f"(d3)
        : "r"(a[0]), "r"(a[1]), "r"(a[2]), "r"(a[3]), "r"(b0), "r"(b1));
}
#define SWZ(o) ((o) ^ (((o) >> 3) & 0x70))

__device__ __forceinline__ void split2(float a, float b, u32& h, u32& l) {
    __nv_bfloat16 ha = __float2bfloat16(a), hb = __float2bfloat16(b);
    __nv_bfloat16 la = __float2bfloat16(a - __bfloat162float(ha));
    __nv_bfloat16 lb = __float2bfloat16(b - __bfloat162float(hb));
    __nv_bfloat162 hh = __halves2bfloat162(ha, hb);
    __nv_bfloat162 ll = __halves2bfloat162(la, lb);
    h = *(u32*)&hh;  l = *(u32*)&ll;
}

// ========== 1) prep: parallel counting-rank sort of enh/inh active rows ======
__global__ __launch_bounds__(1024) void k_prep(const float* __restrict__ enh,
                                               const float* __restrict__ inh) {
    __shared__ float sv[NA];
    int m = blockIdx.x & 1;
    int chunk = blockIdx.x >> 1;
    const float* src = m ? inh : enh;
    int tid = threadIdx.x;

    for (int t = tid; t < NA; t += 1024) {
        int k = (t < NI) ? t : t + NO;
        sv[t] = src[k];
    }
    __syncthreads();

    int el = tid >> 4, jp = tid & 15;
    if (el < 60) {
        int e = chunk * 60 + el;
        float v = sv[e];
        int rank = 0;
        int j0 = jp * 60;
        #pragma unroll 4
        for (int jj = 0; jj < 60; ++jj) {
            int j = j0 + jj;
            float o = sv[j];
            rank += (o < v) || (o == v && j < e);
        }
        #pragma unroll
        for (int off = 1; off < 16; off <<= 1)
            rank += __shfl_xor_sync(0xffffffffu, rank, off);
        if (jp == 0) {
            g_srt[m][rank] = v;
            g_gxr[m][rank] = (e < NI) ? e : e + NO;
        }
    }
}

// ========== 2) fused warmup: 25 steps + c0, 256 threads ======================
// 8 warps: stream st = wid>>1 (enh:+ , enh:- , inh:+ , inh:-), half = wid&1.
// Normalization deferred: conc holds unnormalized values; inv from red[] each iter.
__global__ __launch_bounds__(256) void k_warm(const float* __restrict__ ident,
                                              const float* __restrict__ beta,
                                              const float* __restrict__ delta) {
    __shared__ float tbl[4][NA];
    __shared__ short gxs[2][NA];
    __shared__ short pss[2][NA];
    __shared__ float eP[NA], eM[NA];
    __shared__ float conc[NT];
    __shared__ float P[4][NA];        // preamble: P[0]/P[1] reused as srt0/srt1
    __shared__ float toth[4][2];
    __shared__ float red[8];

    int tid = threadIdx.x, lane = tid & 31, wid = tid >> 5;
    int st = wid >> 1, half = wid & 1;
    int ms = st >> 1;
    float b = beta[0];
    float dsc = delta[0] * INVN;

    for (int i = tid; i < NA; i += 256) {
        float v0 = g_srt[0][i], v1 = g_srt[1][i];
        P[0][i] = v0; P[1][i] = v1;           // temp srt
        tbl[0][i] = expf(b * v0);  tbl[1][i] = expf(-b * v0);
        tbl[2][i] = expf(b * v1);  tbl[3][i] = expf(-b * v1);
        gxs[0][i] = (short)g_gxr[0][i];
        gxs[1][i] = (short)g_gxr[1][i];
        float id = ident[NI + i];
        eP[i] = expf(b * id); eM[i] = expf(-b * id);
    }
    for (int i = tid; i < NT; i += 256) conc[i] = INVN;
    if (tid < 8) red[tid] = (tid == 0) ? 1.f : 0.f;
    __syncthreads();

    for (int i = tid; i < NA; i += 256) {
        float id = ident[NI + i];
        int lo = 0, hi = NA;
        while (lo < hi) { int mid = (lo + hi) >> 1; if (P[0][mid] <= id) lo = mid + 1; else hi = mid; }
        pss[0][i] = (short)lo;
        lo = 0; hi = NA;
        while (lo < hi) { int mid = (lo + hi) >> 1; if (P[1][mid] <= id) lo = mid + 1; else hi = mid; }
        pss[1][i] = (short)lo;
    }
    __syncthreads();

    for (int it = 0; it <= WARM; ++it) {
        bool cp = (it == WARM);
        // inv from previous iteration's partial sums (deterministic order)
        float s = ((red[0] + red[1]) + (red[2] + red[3]))
                + ((red[4] + red[5]) + (red[6] + red[7]));
        float inv = (s > 0.f) ? 1.f / s : 1.f;
        float cA = cp ? 0.f : INVN;

        // ---- phase 1: per-warp scan over 480 elems (15/lane, 2 sub-chains) --
        int e0 = half * 480 + lane * 15;
        float loc[15];
        float runA = 0.f, runB = 0.f;
        #pragma unroll
        for (int i = 0; i < 8; ++i) {
            int k = gxs[ms][e0 + i];
            float cv = (k < NI) ? cA : conc[k] * inv;
            runA += cv * tbl[st][e0 + i];
            loc[i] = runA;
        }
        #pragma unroll
        for (int i = 8; i < 15; ++i) {
            int k = gxs[ms][e0 + i];
            float cv = (k < NI) ? cA : conc[k] * inv;
            runB += cv * tbl[st][e0 + i];
            loc[i] = runB;
        }
        float run = runA + runB;
        float v = run;
        #pragma unroll
        for (int off = 1; off < 32; off <<= 1) {
            float t = __shfl_up_sync(0xffffffffu, v, off);
            if (lane >= off) v += t;
        }
        float excl = v - run;
        #pragma unroll
        for (int i = 0; i < 8; ++i)  P[st][e0 + i] = loc[i] + excl;
        float exclB = excl + runA;
        #pragma unroll
        for (int i = 8; i < 15; ++i) P[st][e0 + i] = loc[i] + exclB;
        if (lane == 31) toth[st][half] = v;
        __syncthreads();

        // ---- phase 2: 960 outputs over 256 threads --------------------------
        float t1 = toth[1][0] + toth[1][1];
        float t3 = toth[3][0] + toth[3][1];
        float lsum = 0.f;
        float nv[4];
        #pragma unroll
        for (int ii = 0; ii < 4; ++ii) {
            int j = tid + ii * 256;
            nv[ii] = 0.f;
            if (j < NA) {
                int pA = pss[0][j], pB = pss[1][j];
                float preA0 = 0.f, preA1 = 0.f, preB2 = 0.f, preB3 = 0.f;
                if (pA) {
                    int ix = pA - 1;
                    float o = (ix >= 480) ? 1.f : 0.f;
                    preA0 = P[0][ix] + o * toth[0][0];
                    preA1 = P[1][ix] + o * toth[1][0];
                }
                if (pB) {
                    int ix = pB - 1;
                    float o = (ix >= 480) ? 1.f : 0.f;
                    preB2 = P[2][ix] + o * toth[2][0];
                    preB3 = P[3][ix] + o * toth[3][0];
                }
                float E = eM[j] * preA0 + eP[j] * (t1 - preA1);
                float I = eM[j] * preB2 + eP[j] * (t3 - preB3);
                float dc = dsc * (E - I);
                float cur = conc[NI + j] * inv;
                if (cp) {
                    g_c0[j] = cur + dc;
                } else {
                    nv[ii] = fmaxf(cur + dc, 0.f);
                    lsum += nv[ii];
                }
            }
        }
        if (cp) break;
        #pragma unroll
        for (int off = 16; off > 0; off >>= 1)
            lsum += __shfl_xor_sync(0xffffffffu, lsum, off);
        if (lane == 0) red[wid] = lsum;
        #pragma unroll
        for (int ii = 0; ii < 4; ++ii) {
            int j = tid + ii * 256;
            if (j < NA) conc[NI + j] = nv[ii];     // unnormalized
        }
        __syncthreads();
    }
}

// ========== 3) weights straight into mma B-fragment layout ===================
__global__ void k_wp(const float* __restrict__ ident, const float* __restrict__ enh,
                     const float* __restrict__ inh, const float* __restrict__ beta,
                     const float* __restrict__ delta) {
    int idx = blockIdx.x * 256 + threadIdx.x;
    if (idx >= 120 * 4 * 32) return;
    int lane = idx & 31;
    int ts = idx >> 5;
    int t = ts >> 2, s = ts & 3;
    int j = t * 8 + (lane >> 2);
    int k0 = s * 16 + (lane & 3) * 2;
    float b = beta[0], dsc = delta[0] * INVN;
    float id = ident[NI + j];

    float wv[4];
    int ks[4] = {k0, k0 + 1, k0 + 8, k0 + 9};
    #pragma unroll
    for (int i = 0; i < 4; ++i) {
        int k = ks[i];
        wv[i] = (expf(-b * fabsf(enh[k] - id)) - expf(-b * fabsf(inh[k] - id))) * dsc;
    }
    uint4 o;
    split2(wv[0], wv[1], o.x, o.z);
    split2(wv[2], wv[3], o.y, o.w);
    g_Wf[idx] = o;
}

// ========== 4) mma.sync fused batch step =====================================
// grid 128 x 256 thr. Warp (wid>>1 = warpM, wid&1 = warpN): 32 rows x 480 cols.
// 4 chunks of 30 n8-tiles, cp.async double-buffered.
// 3 independent accumulator chains per m-tile (hi*hi, lo*hi, hi*lo).
#define CH    30
#define CHB   (CH * 4 * 32 * 16)    // 61440 bytes per chunk
#define OF_AHI 0
#define OF_ALO 16384
#define OF_B   32768                 // 2 * CHB = 122880
#define OF_TS  155648                // 128*64*4 = 32768
#define OF_C0  188416                // 960*4
#define OF_SUM 192256                // 2*128*4
#define OF_SINV 193280               // 128*4
#define SMB    193792

__global__ __launch_bounds__(256) void k_batch(const float* __restrict__ in,
                                               float* __restrict__ out) {
    extern __shared__ __align__(16) char smb[];
    u32 sb = smem_u32(smb);
    float* Ts   = (float*)(smb + OF_TS);
    float* c0s  = (float*)(smb + OF_C0);
    float* sums = (float*)(smb + OF_SUM);
    float* sinv = (float*)(smb + OF_SINV);

    int tid = threadIdx.x, lane = tid & 31, wid = tid >> 5;
    int warpM = wid >> 1, warpN = wid & 1;
    int m0 = blockIdx.x * 128;

    // ---- prefetch B chunk 0 ----
    for (int i = tid; i < CHB / 16; i += 256)
        cpa16(sb + OF_B + i * 16, (const char*)g_Wf + i * 16);
    asm volatile("cp.async.commit_group;" ::: "memory");

    // ---- stage A as swizzled bf16 hi/lo ----
    for (int idx = tid; idx < 128 * 8; idx += 256) {
        int m = idx >> 3, c = idx & 7;
        const float4* p = (const float4*)(in + (size_t)(m0 + m) * 64 + c * 8);
        float4 v0 = p[0], v1 = p[1];
        uint4 H, L;
        split2(v0.x, v0.y, H.x, L.x); split2(v0.z, v0.w, H.y, L.y);
        split2(v1.x, v1.y, H.z, L.z); split2(v1.z, v1.w, H.w, L.w);
        u32 off = SWZ(m * 128 + c * 16);
        *(uint4*)(smb + OF_AHI + off) = H;
        *(uint4*)(smb + OF_ALO + off) = L;
    }
    for (int i = tid; i < NJ; i += 256) c0s[i] = g_c0[i];
    __syncthreads();

    // ---- A fragments (held in registers for the whole kernel) ----
    u32 ah[2][4][4], al[2][4][4];
    {
        int sub = lane >> 3;
        int rr = (lane & 7) + (sub & 1) * 8;
        int kb = (sub >> 1) * 16;
        #pragma unroll
        for (int mt = 0; mt < 2; ++mt)
            #pragma unroll
            for (int s = 0; s < 4; ++s) {
                u32 off = SWZ((warpM * 32 + mt * 16 + rr) * 128 + s * 32 + kb);
                ldmx4(ah[mt][s], sb + OF_AHI + off);
                ldmx4(al[mt][s], sb + OF_ALO + off);
            }
    }

    float rs[2][2] = {{0.f, 0.f}, {0.f, 0.f}};

    for (int c = 0; c < 4; ++c) {
        if (c) __syncthreads();
        if (c < 3) {
            const char* src = (const char*)g_Wf + (size_t)(c + 1) * CHB;
            u32 dstb = sb + OF_B + ((c + 1) & 1) * CHB;
            for (int i = tid; i < CHB / 16; i += 256)
                cpa16(dstb + i * 16, src + i * 16);
            asm volatile("cp.async.commit_group;" ::: "memory");
            asm volatile("cp.async.wait_group 1;" ::: "memory");
        } else {
            asm volatile("cp.async.wait_group 0;" ::: "memory");
        }
        __syncthreads();

        const uint4* Bp = (const uint4*)(smb + OF_B + (c & 1) * CHB);
        #pragma unroll 1
        for (int nt = 0; nt < 15; ++nt) {
            int lt = warpN * 15 + nt;
            int tG = c * CH + lt;
            uint4 bf[4];
            #pragma unroll
            for (int s = 0; s < 4; ++s)
                bf[s] = Bp[(lt * 4 + s) * 32 + lane];

            int colb = tG * 8 + (lane & 3) * 2;
            float c00 = c0s[colb], c01 = c0s[colb + 1];

            #pragma unroll
            for (int mt = 0; mt < 2; ++mt) {
                float h0 = 0.f, h1 = 0.f, h2 = 0.f, h3 = 0.f;   // hi*hi
                float l0 = 0.f, l1 = 0.f, l2 = 0.f, l3 = 0.f;   // lo*hi
                float m0f = 0.f, m1f = 0.f, m2f = 0.f, m3f = 0.f; // hi*lo
                #pragma unroll
                for (int s = 0; s < 4; ++s) {
                    mma_bf16(h0, h1, h2, h3, ah[mt][s], bf[s].x, bf[s].y);
                    mma_bf16(l0, l1, l2, l3, al[mt][s], bf[s].x, bf[s].y);
                    mma_bf16(m0f, m1f, m2f, m3f, ah[mt][s], bf[s].z, bf[s].w);
                }
                float d0 = (h0 + l0) + m0f, d1 = (h1 + l1) + m1f;
                float d2 = (h2 + l2) + m2f, d3 = (h3 + l3) + m3f;
                float t0 = fmaxf(d0 + c00, 0.f), t1 = fmaxf(d1 + c01, 0.f);
                float t2 = fmaxf(d2 + c00, 0.f), t3 = fmaxf(d3 + c01, 0.f);
                rs[mt][0] += t0 + t1;
                rs[mt][1] += t2 + t3;
                if (tG < 8) {
                    int r0 = warpM * 32 + mt * 16 + (lane >> 2);
                    float2 p0 = {t0, t1}, p1 = {t2, t3};
                    *(float2*)&Ts[r0 * 64 + colb] = p0;
                    *(float2*)&Ts[(r0 + 8) * 64 + colb] = p1;
                }
            }
        }
    }

    // ---- rowsums: reduce over the 4 col-lanes of each quad ----
    #pragma unroll
    for (int mt = 0; mt < 2; ++mt)
        #pragma unroll
        for (int h = 0; h < 2; ++h) {
            rs[mt][h] += __shfl_xor_sync(0xffffffffu, rs[mt][h], 1);
            rs[mt][h] += __shfl_xor_sync(0xffffffffu, rs[mt][h], 2);
        }
    if ((lane & 3) == 0) {
        int rq = lane >> 2;
        #pragma unroll
        for (int mt = 0; mt < 2; ++mt) {
            sums[warpN * 128 + warpM * 32 + mt * 16 + rq] = rs[mt][0];
            sums[warpN * 128 + warpM * 32 + mt * 16 + 8 + rq] = rs[mt][1];
        }
    }
    __syncthreads();
    if (tid < 128) {
        float s = sums[tid] + sums[128 + tid];
        sinv[tid] = (s > 0.f) ? 1.f / s : 1.f;
    }
    __syncthreads();

    // ---- normalized coalesced store ----
    for (int idx = tid; idx < 128 * 32; idx += 256) {
        int r = idx >> 5, h2 = idx & 31;
        float2 t = *(float2*)&Ts[r * 64 + h2 * 2];
        float iv = sinv[r];
        float2 o; o.x = t.x * iv; o.y = t.y * iv;
        *(float2*)(out + (size_t)(m0 + r) * 64 + h2 * 2) = o;
    }
}

// -------------------- launch -------------------------------------------------
extern "C" void kernel_launch(void* const* d_in, const int* in_sizes, int n_in,
                              void* d_out, int out_size) {
    const float* inputs = (const float*)d_in[0];
    const float* ident  = (const float*)d_in[1];
    const float* enh    = (const float*)d_in[2];
    const float* inh    = (const float*)d_in[3];
    const float* beta   = (const float*)d_in[4];
    const float* delta  = (const float*)d_in[5];
    float* out = (float*)d_out;
    int B = in_sizes[0] / NI;   // 16384

    static int smset = 0;
    if (!smset) {
        cudaFuncSetAttribute(k_batch, cudaFuncAttributeMaxDynamicSharedMemorySize, SMB);
        smset = 1;
    }

    k_wp<<<60, 256>>>(ident, enh, inh, beta, delta);
    k_prep<<<32, 1024>>>(enh, inh);
    k_warm<<<1, 256>>>(ident, beta, delta);
    k_batch<<<B / 128, 256, SMB>>>(inputs, out);
}